// round 5
// baseline (speedup 1.0000x reference)
#include <cuda_runtime.h>
#include <cuda_bf16.h>
#include <cstdint>
#include <cstddef>

// ---------------- problem constants ----------------
#define DMODEL   768
#define DINNER   1536
#define DSTATE   16
#define DTRANK   48
#define DCONV    4
#define NBATCH   1024
#define SEQL     6
#define NTOK     (NBATCH*SEQL)          // 6144
#define XPN      (DTRANK + 2*DSTATE)    // 80

// ---------------- scratch (device globals; no allocation) ----------------
__device__ float g_xz  [2ull * NTOK * (2*DINNER)]; // in_proj out: [xi | z] per row (stride 3072)
__device__ float g_xc  [2ull * NTOK * DINNER];     // silu(conv(xi))
__device__ float g_xdbl[2ull * NTOK * XPN];        // x_proj out
__device__ float g_dt  [2ull * NTOK * DINNER];     // softplus(dt)
__device__ float g_y   [2ull * NTOK * DINNER];     // scan out * silu(z)
__device__ float g_yo  [2ull * NTOK * DMODEL];     // out_proj out (virtual time order)

// ---------------- helpers ----------------
__device__ __forceinline__ float siluf(float x) {
    return x * (1.f / (1.f + __expf(-x)));
}
__device__ __forceinline__ float softplusf(float x) {
    if (x > 20.f) return x;
    return __logf(1.f + __expf(x));
}

// =======================================================================
// GEMM  C[M,N] = A[M,K] * W[N,K]^T   (both operands K-contiguous, "NT")
// 128x128 tile, BK=16, 256 threads, 8x8 per thread, register prefetch.
// mode 0: A = x input (dir 1 reads time-reversed rows), C = g_xz
// mode 1: A = g_y[dir],                                  C = g_yo[dir]
// =======================================================================
#define GEMM_STORE_TILE() do {                                                        \
    As[k40+0][m0]=pa0.x; As[k40+1][m0]=pa0.y; As[k40+2][m0]=pa0.z; As[k40+3][m0]=pa0.w; \
    As[k40+0][m0+64]=pa1.x; As[k40+1][m0+64]=pa1.y; As[k40+2][m0+64]=pa1.z; As[k40+3][m0+64]=pa1.w; \
    Ws[k40+0][m0]=pw0.x; Ws[k40+1][m0]=pw0.y; Ws[k40+2][m0]=pw0.z; Ws[k40+3][m0]=pw0.w; \
    Ws[k40+0][m0+64]=pw1.x; Ws[k40+1][m0+64]=pw1.y; Ws[k40+2][m0+64]=pw1.z; Ws[k40+3][m0+64]=pw1.w; \
} while (0)

__global__ __launch_bounds__(256)
void gemm_nt(const float* __restrict__ Aext,
             const float* __restrict__ Wf, const float* __restrict__ Wb,
             int M, int N, int K, int mode)
{
    const int dir = blockIdx.z;
    const float* A;
    float* C;
    int rev = 0;
    if (mode == 0) {
        A = Aext;
        C = g_xz + (size_t)dir * ((size_t)NTOK * 2 * DINNER);
        rev = dir;
    } else {
        A = g_y  + (size_t)dir * ((size_t)NTOK * DINNER);
        C = g_yo + (size_t)dir * ((size_t)NTOK * DMODEL);
    }
    const float* W = dir ? Wb : Wf;

    __shared__ __align__(16) float As[16][128];
    __shared__ __align__(16) float Ws[16][128];

    const int tid  = threadIdx.x;
    const int row0 = blockIdx.y * 128;
    const int col0 = blockIdx.x * 128;

    const int m0  = tid >> 2;          // 0..63
    const int k40 = (tid & 3) << 2;    // 0,4,8,12

    // per-slot base pointers (constant across k-tiles)
    int r0 = row0 + m0;
    int r1 = row0 + m0 + 64;
    if (rev) {
        int q = r0 / SEQL; r0 = q * SEQL + (SEQL - 1) - (r0 - q * SEQL);
        q = r1 / SEQL;     r1 = q * SEQL + (SEQL - 1) - (r1 - q * SEQL);
    }
    const float* ap0 = A + (size_t)r0 * K + k40;
    const float* ap1 = A + (size_t)r1 * K + k40;
    const float* wp0 = W + (size_t)(col0 + m0)      * K + k40;
    const float* wp1 = W + (size_t)(col0 + m0 + 64) * K + k40;

    float acc[8][8];
#pragma unroll
    for (int i = 0; i < 8; ++i)
#pragma unroll
        for (int j = 0; j < 8; ++j) acc[i][j] = 0.f;

    const int mB = (tid >> 4) * 8;
    const int nB = (tid & 15) * 8;
    const int nT = K >> 4;

    // prologue: tile 0
    float4 pa0 = *(const float4*)ap0;
    float4 pa1 = *(const float4*)ap1;
    float4 pw0 = *(const float4*)wp0;
    float4 pw1 = *(const float4*)wp1;
    GEMM_STORE_TILE();
    __syncthreads();

    for (int t = 0; t < nT; ++t) {
        const bool more = (t + 1 < nT);
        if (more) {
            const int off = (t + 1) * 16;
            pa0 = *(const float4*)(ap0 + off);
            pa1 = *(const float4*)(ap1 + off);
            pw0 = *(const float4*)(wp0 + off);
            pw1 = *(const float4*)(wp1 + off);
        }
#pragma unroll
        for (int k = 0; k < 16; ++k) {
            float4 a0 = *(const float4*)&As[k][mB];
            float4 a1 = *(const float4*)&As[k][mB + 4];
            float4 b0 = *(const float4*)&Ws[k][nB];
            float4 b1 = *(const float4*)&Ws[k][nB + 4];
            float av[8] = {a0.x, a0.y, a0.z, a0.w, a1.x, a1.y, a1.z, a1.w};
            float bv[8] = {b0.x, b0.y, b0.z, b0.w, b1.x, b1.y, b1.z, b1.w};
#pragma unroll
            for (int i = 0; i < 8; ++i)
#pragma unroll
                for (int j = 0; j < 8; ++j)
                    acc[i][j] = fmaf(av[i], bv[j], acc[i][j]);
        }
        __syncthreads();
        if (more) { GEMM_STORE_TILE(); __syncthreads(); }
    }

#pragma unroll
    for (int i = 0; i < 8; ++i) {
        float* cp = C + (size_t)(row0 + mB + i) * N + col0 + nB;
        float4 o0 = make_float4(acc[i][0], acc[i][1], acc[i][2], acc[i][3]);
        float4 o1 = make_float4(acc[i][4], acc[i][5], acc[i][6], acc[i][7]);
        *(float4*)cp       = o0;
        *(float4*)(cp + 4) = o1;
    }
}

// =======================================================================
// depthwise causal conv (K=4) + SiLU : xi (first half of g_xz) -> g_xc
// =======================================================================
__global__ __launch_bounds__(256)
void conv_kernel(const float* __restrict__ cwf, const float* __restrict__ cwb,
                 const float* __restrict__ cbf, const float* __restrict__ cbb)
{
    const int dir = blockIdx.y;
    const float* cw = dir ? cwb : cwf;   // (4, 1536) taps-major
    const float* cb = dir ? cbb : cbf;
    const float* xi = g_xz + (size_t)dir * ((size_t)NTOK * 2 * DINNER);
    float* xc       = g_xc + (size_t)dir * ((size_t)NTOK * DINNER);

    const int idx = blockIdx.x * 256 + threadIdx.x;   // over NTOK*DINNER
    const int r = idx / DINNER;
    const int d = idx - r * DINNER;
    const int t = r % SEQL;

    float acc = cb[d];
#pragma unroll
    for (int k = 0; k < DCONV; ++k) {
        const int tt = t + k - (DCONV - 1);
        if (tt >= 0)
            acc = fmaf(cw[k * DINNER + d], xi[(size_t)(r + k - (DCONV - 1)) * (2 * DINNER) + d], acc);
    }
    xc[idx] = siluf(acc);
}

// =======================================================================
// x_proj : x_dbl[NTOK,80] = xc[NTOK,1536] * xp[80,1536]^T
// 32 rows x 80 cols per block, 256 threads, TM=2, TN=5.
// =======================================================================
__global__ __launch_bounds__(256)
void xproj_kernel(const float* __restrict__ Wf, const float* __restrict__ Wb)
{
    const int dir = blockIdx.y;
    const float* W = dir ? Wb : Wf;      // (80, 1536)
    const float* A = g_xc   + (size_t)dir * ((size_t)NTOK * DINNER);
    float* C       = g_xdbl + (size_t)dir * ((size_t)NTOK * XPN);

    const int row0 = blockIdx.x * 32;
    __shared__ __align__(16) float As[16][32];
    __shared__ float Ws[16][XPN];

    const int tid = threadIdx.x;
    const int tx = tid & 15, ty = tid >> 4;
    float acc[2][5] = {{0.f,0.f,0.f,0.f,0.f},{0.f,0.f,0.f,0.f,0.f}};

    for (int k0 = 0; k0 < DINNER; k0 += 16) {
        if (tid < 128) {
            const int r = tid >> 2, c4 = (tid & 3) << 2;
            float4 v = *(const float4*)(A + (size_t)(row0 + r) * DINNER + k0 + c4);
            As[c4 + 0][r] = v.x; As[c4 + 1][r] = v.y; As[c4 + 2][r] = v.z; As[c4 + 3][r] = v.w;
        }
#pragma unroll
        for (int i = 0; i < 5; ++i) {
            const int s = tid + i * 256;          // 0..1279
            const int n = s >> 4, c = s & 15;
            Ws[c][n] = W[(size_t)n * DINNER + k0 + c];
        }
        __syncthreads();
#pragma unroll
        for (int k = 0; k < 16; ++k) {
            const float a0 = As[k][ty * 2], a1 = As[k][ty * 2 + 1];
#pragma unroll
            for (int j = 0; j < 5; ++j) {
                const float b = Ws[k][tx * 5 + j];
                acc[0][j] = fmaf(a0, b, acc[0][j]);
                acc[1][j] = fmaf(a1, b, acc[1][j]);
            }
        }
        __syncthreads();
    }
#pragma unroll
    for (int i = 0; i < 2; ++i)
#pragma unroll
        for (int j = 0; j < 5; ++j)
            C[(size_t)(row0 + ty * 2 + i) * XPN + tx * 5 + j] = acc[i][j];
}

// =======================================================================
// dt : softplus( dt_lo[NTOK,48] * dt_w[1536,48]^T + dt_b )  -> g_dt
// block: 32 rows x 128 cols, 256 threads, each thread 16 rows of one col.
// =======================================================================
__global__ __launch_bounds__(256)
void dt_kernel(const float* __restrict__ Wf, const float* __restrict__ Wb,
               const float* __restrict__ Bf, const float* __restrict__ Bb)
{
    const int dir = blockIdx.z;
    const float* W  = dir ? Wb : Wf;   // (1536, 48)
    const float* Bp = dir ? Bb : Bf;   // (1536,)
    const float* xdbl = g_xdbl + (size_t)dir * ((size_t)NTOK * XPN);
    float* out        = g_dt   + (size_t)dir * ((size_t)NTOK * DINNER);

    const int d0 = blockIdx.x * 128;
    const int r0 = blockIdx.y * 32;

    __shared__ __align__(16) float lo[32][48];
    __shared__ float wsT[48][128];

    const int tid = threadIdx.x;
#pragma unroll
    for (int i = 0; i < 6; ++i) {          // 32*48 = 1536 slots
        const int s = tid + i * 256;
        const int r = s / 48, j = s - r * 48;
        lo[r][j] = xdbl[(size_t)(r0 + r) * XPN + j];
    }
#pragma unroll
    for (int i = 0; i < 24; ++i) {         // 128*48 = 6144 slots
        const int s = tid + i * 256;
        const int n = s / 48, j = s - n * 48;
        wsT[j][n] = W[(size_t)(d0 + n) * DTRANK + j];
    }
    __syncthreads();

    const int tx = tid & 127;
    const int ty = tid >> 7;               // 0..1
    float acc[16];
#pragma unroll
    for (int r = 0; r < 16; ++r) acc[r] = 0.f;

#pragma unroll
    for (int j = 0; j < 48; j += 4) {
        const float w0 = wsT[j + 0][tx];
        const float w1 = wsT[j + 1][tx];
        const float w2 = wsT[j + 2][tx];
        const float w3 = wsT[j + 3][tx];
#pragma unroll
        for (int r = 0; r < 16; ++r) {
            float4 l = *(const float4*)&lo[ty * 16 + r][j];
            acc[r] = fmaf(w0, l.x, fmaf(w1, l.y, fmaf(w2, l.z, fmaf(w3, l.w, acc[r]))));
        }
    }
    const float bv = Bp[d0 + tx];
#pragma unroll
    for (int r = 0; r < 16; ++r)
        out[(size_t)(r0 + ty * 16 + r) * DINNER + d0 + tx] = softplusf(acc[r] + bv);
}

// =======================================================================
// selective scan over L=6, 16 states per channel, fused with *silu(z)
// grid: (DINNER/256, NBATCH, 2) ; one thread per channel.
// =======================================================================
__global__ __launch_bounds__(256)
void scan_kernel(const float* __restrict__ Alogf, const float* __restrict__ Alogb,
                 const float* __restrict__ Df,    const float* __restrict__ Db)
{
    const int dir = blockIdx.z;
    const int b   = blockIdx.y;
    const int d   = blockIdx.x * 256 + threadIdx.x;

    const float* Alog = dir ? Alogb : Alogf;
    const float* Dp   = dir ? Db : Df;
    const float* xdbl = g_xdbl + (size_t)dir * ((size_t)NTOK * XPN);
    const float* dtp  = g_dt   + (size_t)dir * ((size_t)NTOK * DINNER);
    const float* xc   = g_xc   + (size_t)dir * ((size_t)NTOK * DINNER);
    const float* zrow = g_xz   + (size_t)dir * ((size_t)NTOK * 2 * DINNER) + DINNER;
    float* out        = g_y    + (size_t)dir * ((size_t)NTOK * DINNER);

    __shared__ float Bs[SEQL][DSTATE];
    __shared__ float Cs[SEQL][DSTATE];
    const int tid = threadIdx.x;
    if (tid < SEQL * DSTATE) {
        const int t = tid >> 4, n = tid & 15;
        Bs[t][n] = xdbl[(size_t)(b * SEQL + t) * XPN + DTRANK + n];
    } else if (tid < 2 * SEQL * DSTATE) {
        const int s = tid - SEQL * DSTATE;
        const int t = s >> 4, n = s & 15;
        Cs[t][n] = xdbl[(size_t)(b * SEQL + t) * XPN + DTRANK + DSTATE + n];
    }
    __syncthreads();

    float An[DSTATE];
#pragma unroll
    for (int n = 0; n < DSTATE; ++n) An[n] = -__expf(Alog[(size_t)d * DSTATE + n]);
    const float Dv = Dp[d];

    float h[DSTATE];
#pragma unroll
    for (int n = 0; n < DSTATE; ++n) h[n] = 0.f;

    for (int t = 0; t < SEQL; ++t) {
        const size_t r = (size_t)(b * SEQL + t);
        const float dtv = dtp[r * DINNER + d];
        const float u   = xc[r * DINNER + d];
        const float du  = dtv * u;
        float y = 0.f;
#pragma unroll
        for (int n = 0; n < DSTATE; ++n) {
            const float dA = __expf(dtv * An[n]);
            h[n] = fmaf(dA, h[n], du * Bs[t][n]);
            y = fmaf(h[n], Cs[t][n], y);
        }
        y = fmaf(u, Dv, y);
        const float zv = zrow[r * (2 * DINNER) + d];
        out[r * DINNER + d] = y * siluf(zv);
    }
}

// =======================================================================
// residual + bidirectional combine (un-reverse backward) + LayerNorm
// =======================================================================
__global__ __launch_bounds__(256)
void ln_kernel(const float* __restrict__ x, const float* __restrict__ gam,
               const float* __restrict__ bet, float* __restrict__ out)
{
    const int row = blockIdx.x;
    const int b = row / SEQL, t = row - b * SEQL;
    const int rrev = b * SEQL + (SEQL - 1) - t;
    const float* yf = g_yo;
    const float* yb = g_yo + (size_t)NTOK * DMODEL;

    const int tid = threadIdx.x;
    float v[3];
    float s = 0.f, s2 = 0.f;
#pragma unroll
    for (int i = 0; i < 3; ++i) {
        const int c = tid + i * 256;
        const float r = x[(size_t)row * DMODEL + c]
                      + yf[(size_t)row * DMODEL + c]
                      + yb[(size_t)rrev * DMODEL + c];
        v[i] = r;
        s += r;
        s2 = fmaf(r, r, s2);
    }
#pragma unroll
    for (int off = 16; off > 0; off >>= 1) {
        s  += __shfl_xor_sync(0xFFFFFFFFu, s,  off);
        s2 += __shfl_xor_sync(0xFFFFFFFFu, s2, off);
    }
    __shared__ float red[2][8];
    const int w = tid >> 5, l = tid & 31;
    if (l == 0) { red[0][w] = s; red[1][w] = s2; }
    __syncthreads();
    s = 0.f; s2 = 0.f;
#pragma unroll
    for (int i = 0; i < 8; ++i) { s += red[0][i]; s2 += red[1][i]; }

    const float inv = 1.f / (float)DMODEL;
    const float mu = s * inv;
    const float var = s2 * inv - mu * mu;
    const float rstd = rsqrtf(var + 1e-5f);
#pragma unroll
    for (int i = 0; i < 3; ++i) {
        const int c = tid + i * 256;
        out[(size_t)row * DMODEL + c] = (v[i] - mu) * rstd * gam[c] + bet[c];
    }
}

// =======================================================================
// launch
// =======================================================================
extern "C" void kernel_launch(void* const* d_in, const int* in_sizes, int n_in,
                              void* d_out, int out_size)
{
    (void)in_sizes; (void)n_in; (void)out_size;
    const float* x     = (const float*)d_in[0];
    const float* f_in  = (const float*)d_in[1];
    const float* f_cw  = (const float*)d_in[2];
    const float* f_cb  = (const float*)d_in[3];
    const float* f_xp  = (const float*)d_in[4];
    const float* f_dtw = (const float*)d_in[5];
    const float* f_dtb = (const float*)d_in[6];
    const float* f_Al  = (const float*)d_in[7];
    const float* f_D   = (const float*)d_in[8];
    const float* f_out = (const float*)d_in[9];
    const float* b_in  = (const float*)d_in[10];
    const float* b_cw  = (const float*)d_in[11];
    const float* b_cb  = (const float*)d_in[12];
    const float* b_xp  = (const float*)d_in[13];
    const float* b_dtw = (const float*)d_in[14];
    const float* b_dtb = (const float*)d_in[15];
    const float* b_Al  = (const float*)d_in[16];
    const float* b_D   = (const float*)d_in[17];
    const float* b_out = (const float*)d_in[18];
    const float* ln_g  = (const float*)d_in[19];
    const float* ln_b  = (const float*)d_in[20];
    float* outp = (float*)d_out;

    // 1) in_proj (both dirs; dir 1 reads time-reversed x)
    dim3 g1((2 * DINNER) / 128, NTOK / 128, 2);
    gemm_nt<<<g1, 256>>>(x, f_in, b_in, NTOK, 2 * DINNER, DMODEL, 0);

    // 2) depthwise causal conv + silu
    dim3 gc((NTOK * DINNER) / 256, 2);
    conv_kernel<<<gc, 256>>>(f_cw, b_cw, f_cb, b_cb);

    // 3) x_proj
    dim3 gx(NTOK / 32, 2);
    xproj_kernel<<<gx, 256>>>(f_xp, b_xp);

    // 4) dt projection + softplus
    dim3 gd(DINNER / 128, NTOK / 32, 2);
    dt_kernel<<<gd, 256>>>(f_dtw, b_dtw, f_dtb, b_dtb);

    // 5) selective scan (+ *silu(z))
    dim3 gs(DINNER / 256, NBATCH, 2);
    scan_kernel<<<gs, 256>>>(f_Al, b_Al, f_D, b_D);

    // 6) out_proj
    dim3 g3(DMODEL / 128, NTOK / 128, 2);
    gemm_nt<<<g3, 256>>>(nullptr, f_out, b_out, NTOK, DMODEL, DINNER, 1);

    // 7) residual + combine + layernorm
    ln_kernel<<<NTOK, 256>>>(x, ln_g, ln_b, outp);
}

// round 9
// speedup vs baseline: 1.6976x; 1.6976x over previous
#include <cuda_runtime.h>
#include <cuda_bf16.h>
#include <cstdint>
#include <cstddef>

// ---------------- problem constants ----------------
#define DMODEL   768
#define DINNER   1536
#define DSTATE   16
#define DTRANK   48
#define DCONV    4
#define NBATCH   1024
#define SEQL     6
#define NTOK     (NBATCH*SEQL)          // 6144
#define XPN      (DTRANK + 2*DSTATE)    // 80

#define KIN3     (3*DMODEL)             // 2304  (split K for in_proj)
#define KOUT3    (3*DINNER)             // 4608  (split K for out_proj)

// ---------------- scratch (device globals; no allocation) ----------------
__device__ float g_xz  [2ull * NTOK * (2*DINNER)]; // in_proj out: [xi | z] per row (stride 3072)
__device__ float g_xc  [2ull * NTOK * DINNER];     // silu(conv(xi))
__device__ float g_xdbl[2ull * NTOK * XPN];        // x_proj out
__device__ float g_dt  [2ull * NTOK * DINNER];     // softplus(dt)
__device__ float g_yo  [2ull * NTOK * DMODEL];     // out_proj out (virtual time order)

// bf16 split operands  (A pattern = [hi|lo|hi], B pattern = [hi|hi|lo])
__device__ __align__(16) __nv_bfloat16 g_xa[(size_t)NTOK * KIN3];            // x split (shared both dirs)
__device__ __align__(16) __nv_bfloat16 g_wi[2ull * (2*DINNER) * KIN3];       // in_proj weights split
__device__ __align__(16) __nv_bfloat16 g_ya[2ull * NTOK * KOUT3];            // scan output split
__device__ __align__(16) __nv_bfloat16 g_wo[2ull * DMODEL * KOUT3];          // out_proj weights split

#define WI_STRIDE ((size_t)(2*DINNER) * KIN3)
#define WO_STRIDE ((size_t)DMODEL * KOUT3)

// ---------------- helpers ----------------
__device__ __forceinline__ float siluf(float x) {
    return x * (1.f / (1.f + __expf(-x)));
}
__device__ __forceinline__ float softplusf(float x) {
    if (x > 20.f) return x;
    return __logf(1.f + __expf(x));
}
__device__ __forceinline__ uint32_t smem_u32(const void* p) {
    uint32_t a;
    asm("{ .reg .u64 t; cvta.to.shared.u64 t, %1; cvt.u32.u64 %0, t; }" : "=r"(a) : "l"(p));
    return a;
}
__device__ __forceinline__ void cp16(uint32_t s, const void* g) {
    asm volatile("cp.async.cg.shared.global [%0], [%1], 16;" :: "r"(s), "l"(g));
}
__device__ __forceinline__ void mma16816(float* c, uint32_t a0, uint32_t a1,
                                         uint32_t a2, uint32_t a3,
                                         uint32_t b0, uint32_t b1) {
    asm volatile(
        "mma.sync.aligned.m16n8k16.row.col.f32.bf16.bf16.f32 "
        "{%0,%1,%2,%3}, {%4,%5,%6,%7}, {%8,%9}, {%0,%1,%2,%3};"
        : "+f"(c[0]), "+f"(c[1]), "+f"(c[2]), "+f"(c[3])
        : "r"(a0), "r"(a1), "r"(a2), "r"(a3), "r"(b0), "r"(b1));
}

// =======================================================================
// fp32 -> bf16 hi/lo split.  bpat=0: [hi|lo|hi] (A), bpat=1: [hi|hi|lo] (B)
// dst_sel: 0=g_xa 1=g_wi(f) 2=g_wi(b) 3=g_wo(f) 4=g_wo(b)
// =======================================================================
__global__ __launch_bounds__(256)
void split_kernel(const float* __restrict__ in, int K, int total, int bpat, int dst_sel)
{
    int idx = blockIdx.x * 256 + threadIdx.x;
    if (idx >= total) return;
    __nv_bfloat16* out;
    switch (dst_sel) {
        case 0: out = g_xa; break;
        case 1: out = g_wi; break;
        case 2: out = g_wi + WI_STRIDE; break;
        case 3: out = g_wo; break;
        default: out = g_wo + WO_STRIDE; break;
    }
    const int r = idx / K, k = idx - r * K;
    const float v = in[idx];
    const __nv_bfloat16 hi = __float2bfloat16(v);
    const __nv_bfloat16 lo = __float2bfloat16(v - __bfloat162float(hi));
    const size_t base = (size_t)r * (3 * K) + k;
    out[base]         = hi;
    out[base + K]     = bpat ? hi : lo;
    out[base + 2 * K] = bpat ? lo : hi;
}

// =======================================================================
// HMMA bf16 GEMM  C[M,N] = A[M,Kb] * W[N,Kb]^T  (both K-contiguous)
// 128x128 CTA tile, BK=32, 256 threads (8 warps, 4x2), warp tile 32x64.
// mma.sync.m16n8k16 bf16 -> fp32. Double-buffered cp.async.
// Smem rows padded to 40 bf16 (80B = 20 banks) => conflict-free frag loads.
// mode 0: in_proj (A=g_xa, dir1 time-reversed rows, C=g_xz, Kb=2304, N=3072)
// mode 1: out_proj (A=g_ya[dir], C=g_yo[dir], Kb=4608, N=768)
// =======================================================================
#define SSTR 40   // smem row stride in bf16 elements

__global__ __launch_bounds__(256)
void gemm_bf16(int mode)
{
    __shared__ __nv_bfloat16 As[2][128][SSTR];
    __shared__ __nv_bfloat16 Bs[2][128][SSTR];

    const int dir = blockIdx.z;
    const int Kb = mode ? KOUT3 : KIN3;
    const int N  = mode ? DMODEL : 2 * DINNER;
    const __nv_bfloat16* A = mode ? (g_ya + (size_t)dir * NTOK * KOUT3) : g_xa;
    const __nv_bfloat16* W = mode ? (g_wo + (size_t)dir * WO_STRIDE)
                                  : (g_wi + (size_t)dir * WI_STRIDE);
    float* C = mode ? (g_yo + (size_t)dir * NTOK * DMODEL)
                    : (g_xz + (size_t)dir * NTOK * (size_t)(2 * DINNER));
    const int rev = (!mode) && dir;

    const int row0 = blockIdx.y * 128;
    const int col0 = blockIdx.x * 128;
    const int tid  = threadIdx.x;
    const int wid  = tid >> 5;
    const int lane = tid & 31;
    const int wm   = wid & 3;      // 4 warps along M (32 rows each)
    const int wn   = wid >> 2;     // 2 warps along N (64 cols each)

    // ---- load slots: thread t handles rows t>>2 and 64+(t>>2), 16B seg t&3
    const int lrow = tid >> 2;         // 0..63
    const int seg  = tid & 3;          // 16B segment within 64B of data
    int ar0 = row0 + lrow, ar1 = row0 + 64 + lrow;
    if (rev) {
        int q = ar0 / SEQL; ar0 = q * SEQL + (SEQL - 1) - (ar0 - q * SEQL);
        q = ar1 / SEQL;     ar1 = q * SEQL + (SEQL - 1) - (ar1 - q * SEQL);
    }
    const __nv_bfloat16* gA0 = A + (size_t)ar0 * Kb + seg * 8;
    const __nv_bfloat16* gA1 = A + (size_t)ar1 * Kb + seg * 8;
    const __nv_bfloat16* gB0 = W + (size_t)(col0 + lrow) * Kb + seg * 8;
    const __nv_bfloat16* gB1 = W + (size_t)(col0 + 64 + lrow) * Kb + seg * 8;

    uint32_t sA0[2], sA1[2], sB0[2], sB1[2];
#pragma unroll
    for (int b = 0; b < 2; ++b) {
        sA0[b] = smem_u32(&As[b][lrow][seg * 8]);
        sA1[b] = smem_u32(&As[b][64 + lrow][seg * 8]);
        sB0[b] = smem_u32(&Bs[b][lrow][seg * 8]);
        sB1[b] = smem_u32(&Bs[b][64 + lrow][seg * 8]);
    }

    float acc[2][8][4];
#pragma unroll
    for (int i = 0; i < 2; ++i)
#pragma unroll
        for (int j = 0; j < 8; ++j)
#pragma unroll
            for (int q = 0; q < 4; ++q) acc[i][j][q] = 0.f;

    const int NC = Kb / 32;

    // prologue: chunks 0,1 into buffers 0,1
#pragma unroll
    for (int c = 0; c < 2; ++c) {
        const size_t off = (size_t)c * 32;
        cp16(sA0[c], gA0 + off); cp16(sA1[c], gA1 + off);
        cp16(sB0[c], gB0 + off); cp16(sB1[c], gB1 + off);
        asm volatile("cp.async.commit_group;" ::: "memory");
    }

    const int g = lane >> 2;            // 0..7
    const int qp = (lane & 3) * 2;      // 0,2,4,6 (element pair start)

    for (int c = 0; c < NC; ++c) {
        const int buf = c & 1;
        asm volatile("cp.async.wait_group 1;" ::: "memory");
        __syncthreads();

#pragma unroll
        for (int ks = 0; ks < 2; ++ks) {
            const int kb = ks * 16;
            uint32_t af[2][4];
#pragma unroll
            for (int mt = 0; mt < 2; ++mt) {
                const int r = wm * 32 + mt * 16 + g;
                af[mt][0] = *(const uint32_t*)&As[buf][r][kb + qp];
                af[mt][1] = *(const uint32_t*)&As[buf][r + 8][kb + qp];
                af[mt][2] = *(const uint32_t*)&As[buf][r][kb + 8 + qp];
                af[mt][3] = *(const uint32_t*)&As[buf][r + 8][kb + 8 + qp];
            }
            uint32_t bf[8][2];
#pragma unroll
            for (int nt = 0; nt < 8; ++nt) {
                const int n = wn * 64 + nt * 8 + g;
                bf[nt][0] = *(const uint32_t*)&Bs[buf][n][kb + qp];
                bf[nt][1] = *(const uint32_t*)&Bs[buf][n][kb + 8 + qp];
            }
#pragma unroll
            for (int mt = 0; mt < 2; ++mt)
#pragma unroll
                for (int nt = 0; nt < 8; ++nt)
                    mma16816(acc[mt][nt], af[mt][0], af[mt][1], af[mt][2], af[mt][3],
                             bf[nt][0], bf[nt][1]);
        }
        __syncthreads();
        if (c + 2 < NC) {
            const size_t off = (size_t)(c + 2) * 32;
            cp16(sA0[buf], gA0 + off); cp16(sA1[buf], gA1 + off);
            cp16(sB0[buf], gB0 + off); cp16(sB1[buf], gB1 + off);
        }
        asm volatile("cp.async.commit_group;" ::: "memory");
    }

    // epilogue: direct float2 stores
#pragma unroll
    for (int mt = 0; mt < 2; ++mt) {
        const int r = row0 + wm * 32 + mt * 16 + g;
#pragma unroll
        for (int nt = 0; nt < 8; ++nt) {
            const int col = col0 + wn * 64 + nt * 8 + qp;
            float2 v0 = make_float2(acc[mt][nt][0], acc[mt][nt][1]);
            float2 v1 = make_float2(acc[mt][nt][2], acc[mt][nt][3]);
            *(float2*)&C[(size_t)r * N + col]       = v0;
            *(float2*)&C[(size_t)(r + 8) * N + col] = v1;
        }
    }
}

// =======================================================================
// depthwise causal conv (K=4) + SiLU : xi (first half of g_xz) -> g_xc
// =======================================================================
__global__ __launch_bounds__(256)
void conv_kernel(const float* __restrict__ cwf, const float* __restrict__ cwb,
                 const float* __restrict__ cbf, const float* __restrict__ cbb)
{
    const int dir = blockIdx.y;
    const float* cw = dir ? cwb : cwf;   // (4, 1536) taps-major
    const float* cb = dir ? cbb : cbf;
    const float* xi = g_xz + (size_t)dir * ((size_t)NTOK * 2 * DINNER);
    float* xc       = g_xc + (size_t)dir * ((size_t)NTOK * DINNER);

    const int idx = blockIdx.x * 256 + threadIdx.x;   // over NTOK*DINNER
    const int r = idx / DINNER;
    const int d = idx - r * DINNER;
    const int t = r % SEQL;

    float acc = cb[d];
#pragma unroll
    for (int k = 0; k < DCONV; ++k) {
        const int tt = t + k - (DCONV - 1);
        if (tt >= 0)
            acc = fmaf(cw[k * DINNER + d], xi[(size_t)(r + k - (DCONV - 1)) * (2 * DINNER) + d], acc);
    }
    xc[idx] = siluf(acc);
}

// =======================================================================
// x_proj : x_dbl[NTOK,80] = xc[NTOK,1536] * xp[80,1536]^T
// =======================================================================
__global__ __launch_bounds__(256)
void xproj_kernel(const float* __restrict__ Wf, const float* __restrict__ Wb)
{
    const int dir = blockIdx.y;
    const float* W = dir ? Wb : Wf;      // (80, 1536)
    const float* A = g_xc   + (size_t)dir * ((size_t)NTOK * DINNER);
    float* C       = g_xdbl + (size_t)dir * ((size_t)NTOK * XPN);

    const int row0 = blockIdx.x * 32;
    __shared__ __align__(16) float As[16][32];
    __shared__ float Ws[16][XPN];

    const int tid = threadIdx.x;
    const int tx = tid & 15, ty = tid >> 4;
    float acc[2][5] = {{0.f,0.f,0.f,0.f,0.f},{0.f,0.f,0.f,0.f,0.f}};

    for (int k0 = 0; k0 < DINNER; k0 += 16) {
        if (tid < 128) {
            const int r = tid >> 2, c4 = (tid & 3) << 2;
            float4 v = *(const float4*)(A + (size_t)(row0 + r) * DINNER + k0 + c4);
            As[c4 + 0][r] = v.x; As[c4 + 1][r] = v.y; As[c4 + 2][r] = v.z; As[c4 + 3][r] = v.w;
        }
#pragma unroll
        for (int i = 0; i < 5; ++i) {
            const int s = tid + i * 256;          // 0..1279
            const int n = s >> 4, c = s & 15;
            Ws[c][n] = W[(size_t)n * DINNER + k0 + c];
        }
        __syncthreads();
#pragma unroll
        for (int k = 0; k < 16; ++k) {
            const float a0 = As[k][ty * 2], a1 = As[k][ty * 2 + 1];
#pragma unroll
            for (int j = 0; j < 5; ++j) {
                const float b = Ws[k][tx * 5 + j];
                acc[0][j] = fmaf(a0, b, acc[0][j]);
                acc[1][j] = fmaf(a1, b, acc[1][j]);
            }
        }
        __syncthreads();
    }
#pragma unroll
    for (int i = 0; i < 2; ++i)
#pragma unroll
        for (int j = 0; j < 5; ++j)
            C[(size_t)(row0 + ty * 2 + i) * XPN + tx * 5 + j] = acc[i][j];
}

// =======================================================================
// dt : softplus( dt_lo[NTOK,48] * dt_w[1536,48]^T + dt_b )  -> g_dt
// =======================================================================
__global__ __launch_bounds__(256)
void dt_kernel(const float* __restrict__ Wf, const float* __restrict__ Wb,
               const float* __restrict__ Bf, const float* __restrict__ Bb)
{
    const int dir = blockIdx.z;
    const float* W  = dir ? Wb : Wf;   // (1536, 48)
    const float* Bp = dir ? Bb : Bf;   // (1536,)
    const float* xdbl = g_xdbl + (size_t)dir * ((size_t)NTOK * XPN);
    float* out        = g_dt   + (size_t)dir * ((size_t)NTOK * DINNER);

    const int d0 = blockIdx.x * 128;
    const int r0 = blockIdx.y * 32;

    __shared__ __align__(16) float lo[32][48];
    __shared__ float wsT[48][128];

    const int tid = threadIdx.x;
#pragma unroll
    for (int i = 0; i < 6; ++i) {
        const int s = tid + i * 256;
        const int r = s / 48, j = s - r * 48;
        lo[r][j] = xdbl[(size_t)(r0 + r) * XPN + j];
    }
#pragma unroll
    for (int i = 0; i < 24; ++i) {
        const int s = tid + i * 256;
        const int n = s / 48, j = s - n * 48;
        wsT[j][n] = W[(size_t)(d0 + n) * DTRANK + j];
    }
    __syncthreads();

    const int tx = tid & 127;
    const int ty = tid >> 7;
    float acc[16];
#pragma unroll
    for (int r = 0; r < 16; ++r) acc[r] = 0.f;

#pragma unroll
    for (int j = 0; j < 48; j += 4) {
        const float w0 = wsT[j + 0][tx];
        const float w1 = wsT[j + 1][tx];
        const float w2 = wsT[j + 2][tx];
        const float w3 = wsT[j + 3][tx];
#pragma unroll
        for (int r = 0; r < 16; ++r) {
            float4 l = *(const float4*)&lo[ty * 16 + r][j];
            acc[r] = fmaf(w0, l.x, fmaf(w1, l.y, fmaf(w2, l.z, fmaf(w3, l.w, acc[r]))));
        }
    }
    const float bv = Bp[d0 + tx];
#pragma unroll
    for (int r = 0; r < 16; ++r)
        out[(size_t)(r0 + ty * 16 + r) * DINNER + d0 + tx] = softplusf(acc[r] + bv);
}

// =======================================================================
// selective scan over L=6; writes bf16 hi/lo split [hi|lo|hi] into g_ya
// =======================================================================
__global__ __launch_bounds__(256)
void scan_kernel(const float* __restrict__ Alogf, const float* __restrict__ Alogb,
                 const float* __restrict__ Df,    const float* __restrict__ Db)
{
    const int dir = blockIdx.z;
    const int b   = blockIdx.y;
    const int d   = blockIdx.x * 256 + threadIdx.x;

    const float* Alog = dir ? Alogb : Alogf;
    const float* Dp   = dir ? Db : Df;
    const float* xdbl = g_xdbl + (size_t)dir * ((size_t)NTOK * XPN);
    const float* dtp  = g_dt   + (size_t)dir * ((size_t)NTOK * DINNER);
    const float* xc   = g_xc   + (size_t)dir * ((size_t)NTOK * DINNER);
    const float* zrow = g_xz   + (size_t)dir * ((size_t)NTOK * 2 * DINNER) + DINNER;
    __nv_bfloat16* ya = g_ya   + (size_t)dir * ((size_t)NTOK * KOUT3);

    __shared__ float Bs[SEQL][DSTATE];
    __shared__ float Cs[SEQL][DSTATE];
    const int tid = threadIdx.x;
    if (tid < SEQL * DSTATE) {
        const int t = tid >> 4, n = tid & 15;
        Bs[t][n] = xdbl[(size_t)(b * SEQL + t) * XPN + DTRANK + n];
    } else if (tid < 2 * SEQL * DSTATE) {
        const int s = tid - SEQL * DSTATE;
        const int t = s >> 4, n = s & 15;
        Cs[t][n] = xdbl[(size_t)(b * SEQL + t) * XPN + DTRANK + DSTATE + n];
    }
    __syncthreads();

    float An[DSTATE];
#pragma unroll
    for (int n = 0; n < DSTATE; ++n) An[n] = -__expf(Alog[(size_t)d * DSTATE + n]);
    const float Dv = Dp[d];

    float h[DSTATE];
#pragma unroll
    for (int n = 0; n < DSTATE; ++n) h[n] = 0.f;

    for (int t = 0; t < SEQL; ++t) {
        const size_t r = (size_t)(b * SEQL + t);
        const float dtv = dtp[r * DINNER + d];
        const float u   = xc[r * DINNER + d];
        const float du  = dtv * u;
        float y = 0.f;
#pragma unroll
        for (int n = 0; n < DSTATE; ++n) {
            const float dA = __expf(dtv * An[n]);
            h[n] = fmaf(dA, h[n], du * Bs[t][n]);
            y = fmaf(h[n], Cs[t][n], y);
        }
        y = fmaf(u, Dv, y);
        const float zv = zrow[r * (2 * DINNER) + d];
        const float v = y * siluf(zv);
        const __nv_bfloat16 hi = __float2bfloat16(v);
        const __nv_bfloat16 lo = __float2bfloat16(v - __bfloat162float(hi));
        const size_t rb = r * (size_t)KOUT3 + d;
        ya[rb]              = hi;
        ya[rb + DINNER]     = lo;
        ya[rb + 2 * DINNER] = hi;
    }
}

// =======================================================================
// residual + bidirectional combine (un-reverse backward) + LayerNorm
// =======================================================================
__global__ __launch_bounds__(256)
void ln_kernel(const float* __restrict__ x, const float* __restrict__ gam,
               const float* __restrict__ bet, float* __restrict__ out)
{
    const int row = blockIdx.x;
    const int b = row / SEQL, t = row - b * SEQL;
    const int rrev = b * SEQL + (SEQL - 1) - t;
    const float* yf = g_yo;
    const float* yb = g_yo + (size_t)NTOK * DMODEL;

    const int tid = threadIdx.x;
    float v[3];
    float s = 0.f, s2 = 0.f;
#pragma unroll
    for (int i = 0; i < 3; ++i) {
        const int c = tid + i * 256;
        const float r = x[(size_t)row * DMODEL + c]
                      + yf[(size_t)row * DMODEL + c]
                      + yb[(size_t)rrev * DMODEL + c];
        v[i] = r;
        s += r;
        s2 = fmaf(r, r, s2);
    }
#pragma unroll
    for (int off = 16; off > 0; off >>= 1) {
        s  += __shfl_xor_sync(0xFFFFFFFFu, s,  off);
        s2 += __shfl_xor_sync(0xFFFFFFFFu, s2, off);
    }
    __shared__ float red[2][8];
    const int w = tid >> 5, l = tid & 31;
    if (l == 0) { red[0][w] = s; red[1][w] = s2; }
    __syncthreads();
    s = 0.f; s2 = 0.f;
#pragma unroll
    for (int i = 0; i < 8; ++i) { s += red[0][i]; s2 += red[1][i]; }

    const float inv = 1.f / (float)DMODEL;
    const float mu = s * inv;
    const float var = s2 * inv - mu * mu;
    const float rstd = rsqrtf(var + 1e-5f);
#pragma unroll
    for (int i = 0; i < 3; ++i) {
        const int c = tid + i * 256;
        out[(size_t)row * DMODEL + c] = (v[i] - mu) * rstd * gam[c] + bet[c];
    }
}

// =======================================================================
// launch
// =======================================================================
extern "C" void kernel_launch(void* const* d_in, const int* in_sizes, int n_in,
                              void* d_out, int out_size)
{
    (void)in_sizes; (void)n_in; (void)out_size;
    const float* x     = (const float*)d_in[0];
    const float* f_in  = (const float*)d_in[1];
    const float* f_cw  = (const float*)d_in[2];
    const float* f_cb  = (const float*)d_in[3];
    const float* f_xp  = (const float*)d_in[4];
    const float* f_dtw = (const float*)d_in[5];
    const float* f_dtb = (const float*)d_in[6];
    const float* f_Al  = (const float*)d_in[7];
    const float* f_D   = (const float*)d_in[8];
    const float* f_out = (const float*)d_in[9];
    const float* b_in  = (const float*)d_in[10];
    const float* b_cw  = (const float*)d_in[11];
    const float* b_cb  = (const float*)d_in[12];
    const float* b_xp  = (const float*)d_in[13];
    const float* b_dtw = (const float*)d_in[14];
    const float* b_dtb = (const float*)d_in[15];
    const float* b_Al  = (const float*)d_in[16];
    const float* b_D   = (const float*)d_in[17];
    const float* b_out = (const float*)d_in[18];
    const float* ln_g  = (const float*)d_in[19];
    const float* ln_b  = (const float*)d_in[20];
    float* outp = (float*)d_out;

    // 0) bf16 hi/lo splits (x + all GEMM weights)
    {
        int tot = NTOK * DMODEL;
        split_kernel<<<(tot + 255) / 256, 256>>>(x, DMODEL, tot, 0, 0);
        tot = (2 * DINNER) * DMODEL;
        split_kernel<<<(tot + 255) / 256, 256>>>(f_in, DMODEL, tot, 1, 1);
        split_kernel<<<(tot + 255) / 256, 256>>>(b_in, DMODEL, tot, 1, 2);
        tot = DMODEL * DINNER;
        split_kernel<<<(tot + 255) / 256, 256>>>(f_out, DINNER, tot, 1, 3);
        split_kernel<<<(tot + 255) / 256, 256>>>(b_out, DINNER, tot, 1, 4);
    }

    // 1) in_proj (HMMA bf16 split GEMM; dir 1 reads time-reversed x)
    {
        dim3 g((2 * DINNER) / 128, NTOK / 128, 2);
        gemm_bf16<<<g, 256>>>(0);
    }

    // 2) depthwise causal conv + silu
    {
        dim3 gc((NTOK * DINNER) / 256, 2);
        conv_kernel<<<gc, 256>>>(f_cw, b_cw, f_cb, b_cb);
    }

    // 3) x_proj
    {
        dim3 gx(NTOK / 32, 2);
        xproj_kernel<<<gx, 256>>>(f_xp, b_xp);
    }

    // 4) dt projection + softplus
    {
        dim3 gd(DINNER / 128, NTOK / 32, 2);
        dt_kernel<<<gd, 256>>>(f_dtw, b_dtw, f_dtb, b_dtb);
    }

    // 5) selective scan (+ *silu(z)); emits bf16 split directly
    {
        dim3 gs(DINNER / 256, NBATCH, 2);
        scan_kernel<<<gs, 256>>>(f_Al, b_Al, f_D, b_D);
    }

    // 6) out_proj (HMMA bf16 split GEMM)
    {
        dim3 g(DMODEL / 128, NTOK / 128, 2);
        gemm_bf16<<<g, 256>>>(1);
    }

    // 7) residual + combine + layernorm
    ln_kernel<<<NTOK, 256>>>(x, ln_g, ln_b, outp);
}

// round 10
// speedup vs baseline: 1.9777x; 1.1650x over previous
#include <cuda_runtime.h>
#include <cuda_bf16.h>
#include <cstdint>
#include <cstddef>

// ---------------- problem constants ----------------
#define DMODEL   768
#define DINNER   1536
#define DSTATE   16
#define DTRANK   48
#define DCONV    4
#define NBATCH   1024
#define SEQL     6
#define NTOK     (NBATCH*SEQL)          // 6144
#define XPN      (DTRANK + 2*DSTATE)    // 80

#define KIN3     (3*DMODEL)             // 2304  (split K for in_proj)
#define KOUT3    (3*DINNER)             // 4608  (split K for out_proj)

// ---------------- scratch (device globals; no allocation) ----------------
__device__ float g_xz  [2ull * NTOK * (2*DINNER)]; // in_proj out: [xi | z] per row (stride 3072)
__device__ float g_xc  [2ull * NTOK * DINNER];     // silu(conv(xi))
__device__ float g_xdbl[2ull * NTOK * XPN];        // x_proj out
__device__ float g_yo  [2ull * NTOK * DMODEL];     // out_proj out (virtual time order)

// bf16 split operands  (A pattern = [hi|lo|hi], B pattern = [hi|hi|lo])
__device__ __align__(16) __nv_bfloat16 g_xa[(size_t)NTOK * KIN3];            // x split (shared both dirs)
__device__ __align__(16) __nv_bfloat16 g_wi[2ull * (2*DINNER) * KIN3];       // in_proj weights split
__device__ __align__(16) __nv_bfloat16 g_ya[2ull * NTOK * KOUT3];            // scan output split
__device__ __align__(16) __nv_bfloat16 g_wo[2ull * DMODEL * KOUT3];          // out_proj weights split

#define WI_STRIDE ((size_t)(2*DINNER) * KIN3)
#define WO_STRIDE ((size_t)DMODEL * KOUT3)

// ---------------- helpers ----------------
__device__ __forceinline__ float siluf(float x) {
    return x * (1.f / (1.f + __expf(-x)));
}
__device__ __forceinline__ float softplusf(float x) {
    if (x > 20.f) return x;
    return __logf(1.f + __expf(x));
}
__device__ __forceinline__ uint32_t smem_u32(const void* p) {
    uint32_t a;
    asm("{ .reg .u64 t; cvta.to.shared.u64 t, %1; cvt.u32.u64 %0, t; }" : "=r"(a) : "l"(p));
    return a;
}
__device__ __forceinline__ void cp16(uint32_t s, const void* g) {
    asm volatile("cp.async.cg.shared.global [%0], [%1], 16;" :: "r"(s), "l"(g));
}
__device__ __forceinline__ void ldmat4(uint32_t& r0, uint32_t& r1, uint32_t& r2,
                                       uint32_t& r3, uint32_t addr) {
    asm volatile("ldmatrix.sync.aligned.m8n8.x4.shared.b16 {%0,%1,%2,%3}, [%4];"
                 : "=r"(r0), "=r"(r1), "=r"(r2), "=r"(r3) : "r"(addr));
}
__device__ __forceinline__ void mma16816(float* c, uint32_t a0, uint32_t a1,
                                         uint32_t a2, uint32_t a3,
                                         uint32_t b0, uint32_t b1) {
    asm volatile(
        "mma.sync.aligned.m16n8k16.row.col.f32.bf16.bf16.f32 "
        "{%0,%1,%2,%3}, {%4,%5,%6,%7}, {%8,%9}, {%0,%1,%2,%3};"
        : "+f"(c[0]), "+f"(c[1]), "+f"(c[2]), "+f"(c[3])
        : "r"(a0), "r"(a1), "r"(a2), "r"(a3), "r"(b0), "r"(b1));
}

// =======================================================================
// fp32 -> bf16 hi/lo split.  bpat=0: [hi|lo|hi] (A), bpat=1: [hi|hi|lo] (B)
// dst_sel: 0=g_xa 1=g_wi(f) 2=g_wi(b) 3=g_wo(f) 4=g_wo(b)
// =======================================================================
__global__ __launch_bounds__(256)
void split_kernel(const float* __restrict__ in, int K, int total, int bpat, int dst_sel)
{
    int idx = blockIdx.x * 256 + threadIdx.x;
    if (idx >= total) return;
    __nv_bfloat16* out;
    switch (dst_sel) {
        case 0: out = g_xa; break;
        case 1: out = g_wi; break;
        case 2: out = g_wi + WI_STRIDE; break;
        case 3: out = g_wo; break;
        default: out = g_wo + WO_STRIDE; break;
    }
    const int r = idx / K, k = idx - r * K;
    const float v = in[idx];
    const __nv_bfloat16 hi = __float2bfloat16(v);
    const __nv_bfloat16 lo = __float2bfloat16(v - __bfloat162float(hi));
    const size_t base = (size_t)r * (3 * K) + k;
    out[base]         = hi;
    out[base + K]     = bpat ? hi : lo;
    out[base + 2 * K] = bpat ? lo : hi;
}

// =======================================================================
// HMMA bf16 GEMM  C[M,N] = A[M,Kb] * W[N,Kb]^T  (both K-contiguous)
// 128x128 CTA tile, BK=64, 256 threads (8 warps 4x2), warp tile 32x64.
// ldmatrix.x4 fragment loads, single __syncthreads per chunk,
// issue-before-compute double buffering. Row stride 144B (conflict-free).
// mode 0: in_proj (A=g_xa, dir1 time-reversed rows, C=g_xz, Kb=2304, N=3072)
// mode 1: out_proj (A=g_ya[dir], C=g_yo[dir], Kb=4608, N=768)
// =======================================================================
#define BK        64
#define SSTRB     144                       // smem row stride bytes
#define OPBYTES   (128 * SSTRB)             // 18432 per operand tile
#define BUFBYTES  (2 * OPBYTES)             // A+B per stage
#define GEMM_SMEM (2 * BUFBYTES)            // 73728

__global__ void __launch_bounds__(256, 2) gemm_bf16(int mode)
{
    extern __shared__ __align__(1024) unsigned char smem[];
    const uint32_t sb = smem_u32(smem);

    const int dir = blockIdx.z;
    const int Kb = mode ? KOUT3 : KIN3;
    const int N  = mode ? DMODEL : 2 * DINNER;
    const __nv_bfloat16* A = mode ? (g_ya + (size_t)dir * NTOK * KOUT3) : g_xa;
    const __nv_bfloat16* W = mode ? (g_wo + (size_t)dir * WO_STRIDE)
                                  : (g_wi + (size_t)dir * WI_STRIDE);
    float* C = mode ? (g_yo + (size_t)dir * NTOK * DMODEL)
                    : (g_xz + (size_t)dir * NTOK * (size_t)(2 * DINNER));
    const int rev = (!mode) && dir;

    const int row0 = blockIdx.y * 128;
    const int col0 = blockIdx.x * 128;
    const int tid  = threadIdx.x;
    const int wid  = tid >> 5;
    const int lane = tid & 31;
    const int wm   = wid & 3;      // 4 warps along M (32 rows each)
    const int wn   = wid >> 2;     // 2 warps along N (64 cols each)

    // ---- cp.async slots: thread covers rows lrow,lrow+64; segs seg*16,seg*16+64
    const int lrow = tid >> 2;
    const int seg  = tid & 3;
    int ar0 = row0 + lrow, ar1 = row0 + 64 + lrow;
    if (rev) {
        int q = ar0 / SEQL; ar0 = q * SEQL + (SEQL - 1) - (ar0 - q * SEQL);
        q = ar1 / SEQL;     ar1 = q * SEQL + (SEQL - 1) - (ar1 - q * SEQL);
    }
    const __nv_bfloat16* gA0 = A + (size_t)ar0 * Kb + seg * 8;
    const __nv_bfloat16* gA1 = A + (size_t)ar1 * Kb + seg * 8;
    const __nv_bfloat16* gB0 = W + (size_t)(col0 + lrow) * Kb + seg * 8;
    const __nv_bfloat16* gB1 = W + (size_t)(col0 + 64 + lrow) * Kb + seg * 8;
    const uint32_t so0 = (uint32_t)(lrow * SSTRB + seg * 16);
    const uint32_t so1 = (uint32_t)((lrow + 64) * SSTRB + seg * 16);

    // ---- ldmatrix per-lane byte offsets (within operand tile)
    const int l = lane;
    const uint32_t aoff = (uint32_t)((wm * 32 + (l & 7) + ((l >> 3) & 1) * 8) * SSTRB
                                     + (l >> 4) * 16);
    const uint32_t boff = (uint32_t)((wn * 64 + (l & 7) + ((l >> 4) & 1) * 8) * SSTRB
                                     + ((l >> 3) & 1) * 16);

    float acc[2][8][4];
#pragma unroll
    for (int i = 0; i < 2; ++i)
#pragma unroll
        for (int j = 0; j < 8; ++j)
#pragma unroll
            for (int q = 0; q < 4; ++q) acc[i][j][q] = 0.f;

    const int NC = Kb / BK;

    // prologue: chunk 0 -> buf 0
    {
        const uint32_t a = sb, b = sb + OPBYTES;
        cp16(a + so0, gA0); cp16(a + so0 + 64, gA0 + 32);
        cp16(a + so1, gA1); cp16(a + so1 + 64, gA1 + 32);
        cp16(b + so0, gB0); cp16(b + so0 + 64, gB0 + 32);
        cp16(b + so1, gB1); cp16(b + so1 + 64, gB1 + 32);
        asm volatile("cp.async.commit_group;" ::: "memory");
    }

    for (int c = 0; c < NC; ++c) {
        asm volatile("cp.async.wait_group 0;" ::: "memory");
        __syncthreads();
        if (c + 1 < NC) {
            const uint32_t a = sb + ((c + 1) & 1) * BUFBYTES;
            const uint32_t b = a + OPBYTES;
            const size_t off = (size_t)(c + 1) * BK;
            cp16(a + so0, gA0 + off); cp16(a + so0 + 64, gA0 + off + 32);
            cp16(a + so1, gA1 + off); cp16(a + so1 + 64, gA1 + off + 32);
            cp16(b + so0, gB0 + off); cp16(b + so0 + 64, gB0 + off + 32);
            cp16(b + so1, gB1 + off); cp16(b + so1 + 64, gB1 + off + 32);
            asm volatile("cp.async.commit_group;" ::: "memory");
        }
        const uint32_t Ab = sb + (c & 1) * BUFBYTES;
        const uint32_t Bb = Ab + OPBYTES;
#pragma unroll
        for (int ks = 0; ks < 4; ++ks) {
            const uint32_t kbyte = ks * 32;
            uint32_t af[2][4];
#pragma unroll
            for (int mt = 0; mt < 2; ++mt)
                ldmat4(af[mt][0], af[mt][1], af[mt][2], af[mt][3],
                       Ab + aoff + kbyte + mt * 16 * SSTRB);
            uint32_t bf[8][2];
#pragma unroll
            for (int p = 0; p < 4; ++p)
                ldmat4(bf[2 * p][0], bf[2 * p][1], bf[2 * p + 1][0], bf[2 * p + 1][1],
                       Bb + boff + kbyte + p * 16 * SSTRB);
#pragma unroll
            for (int mt = 0; mt < 2; ++mt)
#pragma unroll
                for (int nt = 0; nt < 8; ++nt)
                    mma16816(acc[mt][nt], af[mt][0], af[mt][1], af[mt][2], af[mt][3],
                             bf[nt][0], bf[nt][1]);
        }
    }

    // epilogue: direct float2 stores
    const int g  = lane >> 2;
    const int qp = (lane & 3) * 2;
#pragma unroll
    for (int mt = 0; mt < 2; ++mt) {
        const int r = row0 + wm * 32 + mt * 16 + g;
#pragma unroll
        for (int nt = 0; nt < 8; ++nt) {
            const int col = col0 + wn * 64 + nt * 8 + qp;
            *(float2*)&C[(size_t)r * N + col]       = make_float2(acc[mt][nt][0], acc[mt][nt][1]);
            *(float2*)&C[(size_t)(r + 8) * N + col] = make_float2(acc[mt][nt][2], acc[mt][nt][3]);
        }
    }
}

// =======================================================================
// depthwise causal conv (K=4) + SiLU : xi (first half of g_xz) -> g_xc
// =======================================================================
__global__ __launch_bounds__(256)
void conv_kernel(const float* __restrict__ cwf, const float* __restrict__ cwb,
                 const float* __restrict__ cbf, const float* __restrict__ cbb)
{
    const int dir = blockIdx.y;
    const float* cw = dir ? cwb : cwf;   // (4, 1536) taps-major
    const float* cb = dir ? cbb : cbf;
    const float* xi = g_xz + (size_t)dir * ((size_t)NTOK * 2 * DINNER);
    float* xc       = g_xc + (size_t)dir * ((size_t)NTOK * DINNER);

    const int idx = blockIdx.x * 256 + threadIdx.x;   // over NTOK*DINNER
    const int r = idx / DINNER;
    const int d = idx - r * DINNER;
    const int t = r % SEQL;

    float acc = cb[d];
#pragma unroll
    for (int k = 0; k < DCONV; ++k) {
        const int tt = t + k - (DCONV - 1);
        if (tt >= 0)
            acc = fmaf(cw[k * DINNER + d], xi[(size_t)(r + k - (DCONV - 1)) * (2 * DINNER) + d], acc);
    }
    xc[idx] = siluf(acc);
}

// =======================================================================
// x_proj : x_dbl[NTOK,80] = xc[NTOK,1536] * xp[80,1536]^T
// =======================================================================
__global__ __launch_bounds__(256)
void xproj_kernel(const float* __restrict__ Wf, const float* __restrict__ Wb)
{
    const int dir = blockIdx.y;
    const float* W = dir ? Wb : Wf;      // (80, 1536)
    const float* A = g_xc   + (size_t)dir * ((size_t)NTOK * DINNER);
    float* C       = g_xdbl + (size_t)dir * ((size_t)NTOK * XPN);

    const int row0 = blockIdx.x * 32;
    __shared__ __align__(16) float As[16][32];
    __shared__ float Ws[16][XPN];

    const int tid = threadIdx.x;
    const int tx = tid & 15, ty = tid >> 4;
    float acc[2][5] = {{0.f,0.f,0.f,0.f,0.f},{0.f,0.f,0.f,0.f,0.f}};

    for (int k0 = 0; k0 < DINNER; k0 += 16) {
        if (tid < 128) {
            const int r = tid >> 2, c4 = (tid & 3) << 2;
            float4 v = *(const float4*)(A + (size_t)(row0 + r) * DINNER + k0 + c4);
            As[c4 + 0][r] = v.x; As[c4 + 1][r] = v.y; As[c4 + 2][r] = v.z; As[c4 + 3][r] = v.w;
        }
#pragma unroll
        for (int i = 0; i < 5; ++i) {
            const int s = tid + i * 256;          // 0..1279
            const int n = s >> 4, c = s & 15;
            Ws[c][n] = W[(size_t)n * DINNER + k0 + c];
        }
        __syncthreads();
#pragma unroll
        for (int k = 0; k < 16; ++k) {
            const float a0 = As[k][ty * 2], a1 = As[k][ty * 2 + 1];
#pragma unroll
            for (int j = 0; j < 5; ++j) {
                const float b = Ws[k][tx * 5 + j];
                acc[0][j] = fmaf(a0, b, acc[0][j]);
                acc[1][j] = fmaf(a1, b, acc[1][j]);
            }
        }
        __syncthreads();
    }
#pragma unroll
    for (int i = 0; i < 2; ++i)
#pragma unroll
        for (int j = 0; j < 5; ++j)
            C[(size_t)(row0 + ty * 2 + i) * XPN + tx * 5 + j] = acc[i][j];
}

// =======================================================================
// fused dt + selective scan + gate; writes bf16 split [hi|lo|hi] to g_ya
// grid (DINNER/256, NBATCH/16, 2); 256 threads; 16 batches per block.
// dt_w slice staged smem->regs once per block; dA via power chain when
// A == -(1..16) (always true for this model), guarded fallback otherwise.
// =======================================================================
#define SCAN_BG   16
#define WT_PAD    257
#define SCAN_SMEM ((48 * WT_PAD + SEQL * XPN) * 4)   // 51264 bytes

__global__ __launch_bounds__(256)
void scan_kernel(const float* __restrict__ Alogf, const float* __restrict__ Alogb,
                 const float* __restrict__ Df,    const float* __restrict__ Db,
                 const float* __restrict__ dtwf,  const float* __restrict__ dtwb,
                 const float* __restrict__ dtbf,  const float* __restrict__ dtbb)
{
    extern __shared__ float ssm[];
    float* wsT = ssm;                       // [48][257] transposed dt_w slice
    float* xs  = ssm + 48 * WT_PAD;         // [6][80] xdbl rows of current batch

    const int dir = blockIdx.z;
    const int d0  = blockIdx.x * 256;
    const int b0  = blockIdx.y * SCAN_BG;
    const int tid = threadIdx.x;
    const int d   = d0 + tid;

    const float* Wdt = dir ? dtwb : dtwf;   // (1536, 48)
    // coalesced load of W slice, transposed store (near conflict-free)
#pragma unroll
    for (int i = 0; i < 48; ++i) {
        const int s = tid + i * 256;
        const int r = s / 48, c = s - r * 48;
        wsT[c * WT_PAD + r] = Wdt[(size_t)(d0 + r) * DTRANK + c];
    }
    __syncthreads();
    float w[48];
#pragma unroll
    for (int j = 0; j < 48; ++j) w[j] = wsT[j * WT_PAD + tid];

    const float* Alog = dir ? Alogb : Alogf;
    const float* Dp   = dir ? Db : Df;
    const float* dtb  = dir ? dtbb : dtbf;

    float An[DSTATE];
    bool fast = true;
#pragma unroll
    for (int n = 0; n < DSTATE; ++n) {
        An[n] = -__expf(Alog[(size_t)d * DSTATE + n]);
        fast = fast && (fabsf(An[n] + (float)(n + 1)) < 1e-4f * (float)(n + 1));
    }
    const float Dv   = Dp[d];
    const float bias = dtb[d];

    const float* xdbl = g_xdbl + (size_t)dir * NTOK * XPN;
    const float* xc   = g_xc   + (size_t)dir * NTOK * DINNER;
    const float* zb   = g_xz   + (size_t)dir * NTOK * (size_t)(2 * DINNER) + DINNER;
    __nv_bfloat16* ya = g_ya   + (size_t)dir * NTOK * (size_t)KOUT3;

    for (int bi = 0; bi < SCAN_BG; ++bi) {
        const int b = b0 + bi;
        __syncthreads();
        for (int s = tid; s < SEQL * XPN; s += 256)
            xs[s] = xdbl[(size_t)(b * SEQL) * XPN + s];
        __syncthreads();

        float u[SEQL], z[SEQL];
#pragma unroll
        for (int t = 0; t < SEQL; ++t) {
            u[t] = xc[(size_t)(b * SEQL + t) * DINNER + d];
            z[t] = zb[(size_t)(b * SEQL + t) * (2 * DINNER) + d];
        }

        float h[DSTATE];
#pragma unroll
        for (int n = 0; n < DSTATE; ++n) h[n] = 0.f;

#pragma unroll
        for (int t = 0; t < SEQL; ++t) {
            const float* xr = xs + t * XPN;
            float acc = bias;
#pragma unroll
            for (int j = 0; j < 48; j += 4) {
                const float4 l4 = *(const float4*)(xr + j);
                acc = fmaf(w[j], l4.x, fmaf(w[j+1], l4.y,
                      fmaf(w[j+2], l4.z, fmaf(w[j+3], l4.w, acc))));
            }
            const float dtv = softplusf(acc);
            const float du  = dtv * u[t];
            float y = 0.f;
            if (fast) {
                const float q = __expf(-dtv);
                float dA = 1.f;
#pragma unroll
                for (int n = 0; n < DSTATE; ++n) {
                    dA *= q;                                  // = exp(-dtv*(n+1))
                    h[n] = fmaf(dA, h[n], du * xr[DTRANK + n]);
                    y = fmaf(h[n], xr[DTRANK + DSTATE + n], y);
                }
            } else {
#pragma unroll
                for (int n = 0; n < DSTATE; ++n) {
                    const float dA = __expf(dtv * An[n]);
                    h[n] = fmaf(dA, h[n], du * xr[DTRANK + n]);
                    y = fmaf(h[n], xr[DTRANK + DSTATE + n], y);
                }
            }
            y = fmaf(u[t], Dv, y);
            const float v = y * siluf(z[t]);
            const __nv_bfloat16 hi = __float2bfloat16(v);
            const __nv_bfloat16 lo = __float2bfloat16(v - __bfloat162float(hi));
            const size_t rb = (size_t)(b * SEQL + t) * KOUT3 + d;
            ya[rb]              = hi;
            ya[rb + DINNER]     = lo;
            ya[rb + 2 * DINNER] = hi;
        }
    }
}

// =======================================================================
// residual + bidirectional combine (un-reverse backward) + LayerNorm
// =======================================================================
__global__ __launch_bounds__(256)
void ln_kernel(const float* __restrict__ x, const float* __restrict__ gam,
               const float* __restrict__ bet, float* __restrict__ out)
{
    const int row = blockIdx.x;
    const int b = row / SEQL, t = row - b * SEQL;
    const int rrev = b * SEQL + (SEQL - 1) - t;
    const float* yf = g_yo;
    const float* yb = g_yo + (size_t)NTOK * DMODEL;

    const int tid = threadIdx.x;
    float v[3];
    float s = 0.f, s2 = 0.f;
#pragma unroll
    for (int i = 0; i < 3; ++i) {
        const int c = tid + i * 256;
        const float r = x[(size_t)row * DMODEL + c]
                      + yf[(size_t)row * DMODEL + c]
                      + yb[(size_t)rrev * DMODEL + c];
        v[i] = r;
        s += r;
        s2 = fmaf(r, r, s2);
    }
#pragma unroll
    for (int off = 16; off > 0; off >>= 1) {
        s  += __shfl_xor_sync(0xFFFFFFFFu, s,  off);
        s2 += __shfl_xor_sync(0xFFFFFFFFu, s2, off);
    }
    __shared__ float red[2][8];
    const int w = tid >> 5, ln = tid & 31;
    if (ln == 0) { red[0][w] = s; red[1][w] = s2; }
    __syncthreads();
    s = 0.f; s2 = 0.f;
#pragma unroll
    for (int i = 0; i < 8; ++i) { s += red[0][i]; s2 += red[1][i]; }

    const float inv = 1.f / (float)DMODEL;
    const float mu = s * inv;
    const float var = s2 * inv - mu * mu;
    const float rstd = rsqrtf(var + 1e-5f);
#pragma unroll
    for (int i = 0; i < 3; ++i) {
        const int c = tid + i * 256;
        out[(size_t)row * DMODEL + c] = (v[i] - mu) * rstd * gam[c] + bet[c];
    }
}

// =======================================================================
// launch
// =======================================================================
extern "C" void kernel_launch(void* const* d_in, const int* in_sizes, int n_in,
                              void* d_out, int out_size)
{
    (void)in_sizes; (void)n_in; (void)out_size;
    const float* x     = (const float*)d_in[0];
    const float* f_in  = (const float*)d_in[1];
    const float* f_cw  = (const float*)d_in[2];
    const float* f_cb  = (const float*)d_in[3];
    const float* f_xp  = (const float*)d_in[4];
    const float* f_dtw = (const float*)d_in[5];
    const float* f_dtb = (const float*)d_in[6];
    const float* f_Al  = (const float*)d_in[7];
    const float* f_D   = (const float*)d_in[8];
    const float* f_out = (const float*)d_in[9];
    const float* b_in  = (const float*)d_in[10];
    const float* b_cw  = (const float*)d_in[11];
    const float* b_cb  = (const float*)d_in[12];
    const float* b_xp  = (const float*)d_in[13];
    const float* b_dtw = (const float*)d_in[14];
    const float* b_dtb = (const float*)d_in[15];
    const float* b_Al  = (const float*)d_in[16];
    const float* b_D   = (const float*)d_in[17];
    const float* b_out = (const float*)d_in[18];
    const float* ln_g  = (const float*)d_in[19];
    const float* ln_b  = (const float*)d_in[20];
    float* outp = (float*)d_out;

    static bool attr_done = false;
    if (!attr_done) {
        cudaFuncSetAttribute(gemm_bf16, cudaFuncAttributeMaxDynamicSharedMemorySize, GEMM_SMEM);
        cudaFuncSetAttribute(scan_kernel, cudaFuncAttributeMaxDynamicSharedMemorySize, SCAN_SMEM);
        attr_done = true;
    }

    // 0) bf16 hi/lo splits (x + all GEMM weights)
    {
        int tot = NTOK * DMODEL;
        split_kernel<<<(tot + 255) / 256, 256>>>(x, DMODEL, tot, 0, 0);
        tot = (2 * DINNER) * DMODEL;
        split_kernel<<<(tot + 255) / 256, 256>>>(f_in, DMODEL, tot, 1, 1);
        split_kernel<<<(tot + 255) / 256, 256>>>(b_in, DMODEL, tot, 1, 2);
        tot = DMODEL * DINNER;
        split_kernel<<<(tot + 255) / 256, 256>>>(f_out, DINNER, tot, 1, 3);
        split_kernel<<<(tot + 255) / 256, 256>>>(b_out, DINNER, tot, 1, 4);
    }

    // 1) in_proj (HMMA bf16 split GEMM; dir 1 reads time-reversed x)
    {
        dim3 g((2 * DINNER) / 128, NTOK / 128, 2);
        gemm_bf16<<<g, 256, GEMM_SMEM>>>(0);
    }

    // 2) depthwise causal conv + silu
    {
        dim3 gc((NTOK * DINNER) / 256, 2);
        conv_kernel<<<gc, 256>>>(f_cw, b_cw, f_cb, b_cb);
    }

    // 3) x_proj
    {
        dim3 gx(NTOK / 32, 2);
        xproj_kernel<<<gx, 256>>>(f_xp, b_xp);
    }

    // 4) fused dt + selective scan + gate (emits bf16 split)
    {
        dim3 gs(DINNER / 256, NBATCH / SCAN_BG, 2);
        scan_kernel<<<gs, 256, SCAN_SMEM>>>(f_Al, b_Al, f_D, b_D,
                                            f_dtw, b_dtw, f_dtb, b_dtb);
    }

    // 5) out_proj (HMMA bf16 split GEMM)
    {
        dim3 g(DMODEL / 128, NTOK / 128, 2);
        gemm_bf16<<<g, 256, GEMM_SMEM>>>(1);
    }

    // 6) residual + combine + layernorm
    ln_kernel<<<NTOK, 256>>>(x, ln_g, ln_b, outp);
}